// round 4
// baseline (speedup 1.0000x reference)
#include <cuda_runtime.h>

// GCN collapse: output[f2] = b2[f2] + (1/N) * sum_f g[f] * W2[f][f2]
//   g[f]   = sum_r w[r] * relu(s1[r]*W1[f] + b1[f])
//   s1[c]  = dinv[c]*( sum_{edges e: col=c} dinv[row_e]*x[row_e] ) + dinv[c]^2 * x[c]
//   w[r]   = dinv[r]*( sum_{edges e: row=r} dinv[col_e] + dinv[r] )
//   dinv[i]= rsqrt(deg_in[i] + 1)   (self loops)

#define MAX_N 100000
#define HID   128

__device__ unsigned int g_deg[MAX_N];
__device__ float g_dinv[MAX_N];
__device__ float g_s1[MAX_N];   // accumulates sum dinv[row]*x[row] into col
__device__ float g_t[MAX_N];    // accumulates sum dinv[col] into row
__device__ float g_g[HID];

__global__ void k_zero_deg(int n) {
    int i = blockIdx.x * blockDim.x + threadIdx.x;
    if (i < n) g_deg[i] = 0u;
}

__global__ void k_deg(const int* __restrict__ col, int E) {
    int idx = blockIdx.x * blockDim.x + threadIdx.x;
    int e = idx * 4;
    if (e >= E) return;
    if (e + 3 < E) {
        int4 c = *reinterpret_cast<const int4*>(col + e);
        atomicAdd(&g_deg[c.x], 1u);
        atomicAdd(&g_deg[c.y], 1u);
        atomicAdd(&g_deg[c.z], 1u);
        atomicAdd(&g_deg[c.w], 1u);
    } else {
        for (; e < E; e++) atomicAdd(&g_deg[col[e]], 1u);
    }
}

__global__ void k_dinv(int n) {
    int i = blockIdx.x * blockDim.x + threadIdx.x;
    if (i >= n) return;
    g_dinv[i] = rsqrtf((float)g_deg[i] + 1.0f);
    g_s1[i] = 0.0f;
    g_t[i]  = 0.0f;
    if (i < HID) g_g[i] = 0.0f;
}

__global__ void k_scatter(const int* __restrict__ row, const int* __restrict__ col,
                          const float* __restrict__ x, int E) {
    int idx = blockIdx.x * blockDim.x + threadIdx.x;
    int e = idx * 4;
    if (e >= E) return;
    if (e + 3 < E) {
        int4 r = *reinterpret_cast<const int4*>(row + e);
        int4 c = *reinterpret_cast<const int4*>(col + e);
        float dr0 = g_dinv[r.x], dr1 = g_dinv[r.y], dr2 = g_dinv[r.z], dr3 = g_dinv[r.w];
        float dc0 = g_dinv[c.x], dc1 = g_dinv[c.y], dc2 = g_dinv[c.z], dc3 = g_dinv[c.w];
        float x0 = __ldg(x + r.x), x1 = __ldg(x + r.y), x2 = __ldg(x + r.z), x3 = __ldg(x + r.w);
        atomicAdd(&g_s1[c.x], dr0 * x0);
        atomicAdd(&g_s1[c.y], dr1 * x1);
        atomicAdd(&g_s1[c.z], dr2 * x2);
        atomicAdd(&g_s1[c.w], dr3 * x3);
        atomicAdd(&g_t[r.x], dc0);
        atomicAdd(&g_t[r.y], dc1);
        atomicAdd(&g_t[r.z], dc2);
        atomicAdd(&g_t[r.w], dc3);
    } else {
        for (; e < E; e++) {
            int r = row[e], c = col[e];
            atomicAdd(&g_s1[c], g_dinv[r] * __ldg(x + r));
            atomicAdd(&g_t[r], g_dinv[c]);
        }
    }
}

// Block = 128 threads (one per hidden feature). Each block handles NPB nodes.
__global__ void k_reduce(const float* __restrict__ x,
                         const float* __restrict__ W1,
                         const float* __restrict__ b1,
                         int n, int npb) {
    __shared__ float ss[128];
    __shared__ float sw[128];
    int f = threadIdx.x;
    float W1f = W1[f];
    float b1f = b1[f];
    float acc = 0.0f;
    int base = blockIdx.x * npb;
    int end = base + npb;
    if (end > n) end = n;
    for (int t0 = base; t0 < end; t0 += 128) {
        int i = t0 + f;
        if (i < end) {
            float d = g_dinv[i];
            ss[f] = fmaf(d, g_s1[i], d * d * __ldg(x + i));
            sw[f] = d * (g_t[i] + d);
        } else {
            ss[f] = 0.0f;
            sw[f] = 0.0f;  // zero weight -> node contributes nothing
        }
        __syncthreads();
        #pragma unroll 16
        for (int j = 0; j < 128; j++) {
            acc += sw[j] * fmaxf(fmaf(ss[j], W1f, b1f), 0.0f);
        }
        __syncthreads();
    }
    atomicAdd(&g_g[f], acc);
}

__global__ void k_out(const float* __restrict__ W2,
                      const float* __restrict__ b2,
                      float* __restrict__ out,
                      int outdim, float invn) {
    int f2 = blockIdx.x * blockDim.x + threadIdx.x;
    if (f2 >= outdim) return;
    float acc = 0.0f;
    #pragma unroll 16
    for (int f = 0; f < HID; f++) {
        acc = fmaf(g_g[f], __ldg(W2 + f * outdim + f2), acc);
    }
    out[f2] = fmaf(acc, invn, b2[f2]);
}

extern "C" void kernel_launch(void* const* d_in, const int* in_sizes, int n_in,
                              void* d_out, int out_size) {
    const float* x  = (const float*)d_in[0];
    const int*   ei = (const int*)d_in[1];
    const float* W1 = (const float*)d_in[2];
    const float* b1 = (const float*)d_in[3];
    const float* W2 = (const float*)d_in[4];
    const float* b2 = (const float*)d_in[5];
    float* out = (float*)d_out;

    int n = in_sizes[0];            // 100000 (x is [N,1])
    int E = in_sizes[1] / 2;        // 1.6M
    int outdim = in_sizes[5];       // 400

    const int* row = ei;        // edge_index[0]
    const int* col = ei + E;    // edge_index[1]

    int tE = (E + 3) / 4;
    dim3 bs(256);
    dim3 gN((n + 255) / 256);
    dim3 gE((tE + 255) / 256);

    k_zero_deg<<<gN, bs>>>(n);
    k_deg<<<gE, bs>>>(col, E);
    k_dinv<<<gN, bs>>>(n);
    k_scatter<<<gE, bs>>>(row, col, x, E);

    const int NPB = 512;
    int gR = (n + NPB - 1) / NPB;
    k_reduce<<<gR, 128>>>(x, W1, b1, n, NPB);

    k_out<<<(outdim + 127) / 128, 128>>>(W2, b2, out, outdim, 1.0f / (float)n);
}